// round 10
// baseline (speedup 1.0000x reference)
#include <cuda_runtime.h>

// CRF NLL: B=1024, T=4096, K=16
// d_in[0]=feats [B,T,K] f32, d_in[1]=tags [B,T] i32, d_in[2]=transitions [K,K] f32
// out: [B] f32
//
// 8 lanes per element; lane r owns states 2r, 2r+1. Probability-domain scan:
//   p_{t+1}[j] = exp(feat_t[j]) * sum_i expT[j][i] * p_t[i]
// Exchange is 14 independent shfl_xor(width=8) (no smem on the chain).
// Matvec uses packed fma.rn.f32x2 on (p_2m, p_2m+1) pairs.
// Exact pow2 renorm (stale max, integer esum) folded into the ef scaling.

#define T_LEN 4096
#define KTAG 16
#define TILE 8
#define START_TAG 14
#define STOP_TAG 15

typedef unsigned long long ull;

__device__ __forceinline__ ull pk2(float lo, float hi) {
    ull d; asm("mov.b64 %0,{%1,%2};" : "=l"(d) : "f"(lo), "f"(hi)); return d;
}
__device__ __forceinline__ void upk2(ull v, float& lo, float& hi) {
    asm("mov.b64 {%0,%1},%2;" : "=f"(lo), "=f"(hi) : "l"(v));
}
__device__ __forceinline__ ull fma2(ull a, ull b, ull c) {
    ull d; asm("fma.rn.f32x2 %0,%1,%2,%3;" : "=l"(d) : "l"(a), "l"(b), "l"(c)); return d;
}
__device__ __forceinline__ ull mul2(ull a, ull b) {
    ull d; asm("mul.rn.f32x2 %0,%1,%2;" : "=l"(d) : "l"(a), "l"(b)); return d;
}
__device__ __forceinline__ ull add2(ull a, ull b) {
    ull d; asm("add.rn.f32x2 %0,%1,%2;" : "=l"(d) : "l"(a), "l"(b)); return d;
}

__global__ __launch_bounds__(32, 8)
void crf_nll_kernel(const float* __restrict__ feats,
                    const int* __restrict__ tags,
                    const float* __restrict__ trans,
                    float* __restrict__ out) {
    __shared__ float sExpT[256];   // exp(trans[j][i])
    __shared__ float sLogT[256];   // trans[j][i]

    int tid = threadIdx.x;         // one warp per block
    for (int i = tid; i < 256; i += 32) {
        float tv = trans[i];
        sLogT[i] = tv;
        sExpT[i] = __expf(tv);     // exp(-10000) -> 0: correct masking
    }
    __syncthreads();

    int r  = tid & 7;              // lane within 8-lane group
    int g  = tid >> 3;             // group 0..3
    int b  = blockIdx.x * 4 + g;
    int j0 = 2 * r, j1 = 2 * r + 1;

    // Packed row pairs, stored in SHUFFLE ORDER: slot kk holds the pair of
    // M-columns owned by lane (r ^ kk), so all loop indices are compile-time.
    ull A0k[8], A1k[8];
    #pragma unroll
    for (int kk = 0; kk < 8; kk++) {
        int m = r ^ kk;
        A0k[kk] = pk2(sExpT[j0 * 16 + 2 * m], sExpT[j0 * 16 + 2 * m + 1]);
        A1k[kk] = pk2(sExpT[j1 * 16 + 2 * m], sExpT[j1 * 16 + 2 * m + 1]);
    }
    float Mstop0 = sExpT[STOP_TAG * 16 + j0];
    float Mstop1 = sExpT[STOP_TAG * 16 + j1];

    const float* fbase = feats + (size_t)b * T_LEN * KTAG;
    const int*   tptr  = tags  + (size_t)b * T_LEN;

    // alpha_0: 1 at START(=14=j0 of lane 7), 0 elsewhere
    float p0 = (r == 7) ? 1.0f : 0.0f;
    float p1 = 0.0f;

    int   esum = 0;           // exact pow2 scale accumulator
    float gold = 0.0f;
    int   prevtag = START_TAG;
    float stale_m = 1.0f;     // group max, measured 2 steps before applied

    float2 fA[TILE], fB[TILE];
    int    gA[TILE], gB[TILE];

    #pragma unroll
    for (int u = 0; u < TILE; u++)
        fA[u] = *reinterpret_cast<const float2*>(fbase + u * KTAG + j0);
    {
        const int4* tp4 = reinterpret_cast<const int4*>(tptr);
        int4 v = tp4[0]; gA[0]=v.x; gA[1]=v.y; gA[2]=v.z; gA[3]=v.w;
        int4 w = tp4[1]; gA[4]=w.x; gA[5]=w.y; gA[6]=w.z; gA[7]=w.w;
    }

    const int NT = T_LEN / TILE;   // 512
    #pragma unroll 1
    for (int tile = 0; tile < NT; tile++) {
        if (tile + 1 < NT) {
            int base = (tile + 1) * TILE;
            #pragma unroll
            for (int u = 0; u < TILE; u++)
                fB[u] = *reinterpret_cast<const float2*>(fbase + (base + u) * KTAG + j0);
            const int4* tp4 = reinterpret_cast<const int4*>(tptr + base);
            int4 v = tp4[0]; gB[0]=v.x; gB[1]=v.y; gB[2]=v.z; gB[3]=v.w;
            int4 w = tp4[1]; gB[4]=w.x; gB[5]=w.y; gB[6]=w.z; gB[7]=w.w;
        }
        int tbase = tile * TILE;

        #pragma unroll
        for (int u = 0; u < TILE; u++) {
            float2 f = fA[u];
            int   tg = gA[u];
            float ef0 = __expf(f.x);
            float ef1 = __expf(f.y);

            // exact pow2 renorm, stale scale (known 2 steps early, off chain)
            if ((u & 3) == 3) {
                int e = (__float_as_int(stale_m) >> 23) & 255;
                float sc = __int_as_float((254 - e) << 23);  // 2^(127-e), exact
                ef0 *= sc; ef1 *= sc;
                esum += e - 127;
            }

            // gather all 8 state-pairs via xor shuffles (width 8), pack each
            ull Pk[8];
            Pk[0] = pk2(p0, p1);
            #pragma unroll
            for (int kk = 1; kk < 8; kk++) {
                float a = __shfl_xor_sync(0xffffffffu, p0, kk, 8);
                float c = __shfl_xor_sync(0xffffffffu, p1, kk, 8);
                Pk[kk] = pk2(a, c);
            }

            // out_j = sum_m Arow[j][pair m] . (p_2m, p_2m+1), packed FMAs
            ull a0 = mul2(A0k[0], Pk[0]);
            ull b0 = mul2(A0k[1], Pk[1]);
            ull a1 = mul2(A1k[0], Pk[0]);
            ull b1 = mul2(A1k[1], Pk[1]);
            #pragma unroll
            for (int kk = 2; kk < 8; kk += 2) {
                a0 = fma2(A0k[kk],     Pk[kk],     a0);
                b0 = fma2(A0k[kk + 1], Pk[kk + 1], b0);
                a1 = fma2(A1k[kk],     Pk[kk],     a1);
                b1 = fma2(A1k[kk + 1], Pk[kk + 1], b1);
            }
            ull s0 = add2(a0, b0);
            ull s1 = add2(a1, b1);
            float s0l, s0h, s1l, s1h;
            upk2(s0, s0l, s0h);
            upk2(s1, s1l, s1h);
            float pn0 = (s0l + s0h) * ef0;
            float pn1 = (s1l + s1h) * ef1;

            // measure group max for use 2 steps later (off-chain butterfly)
            if ((u & 3) == 1) {
                float lm = fmaxf(pn0, pn1);
                lm = fmaxf(lm, __shfl_xor_sync(0xffffffffu, lm, 1, 8));
                lm = fmaxf(lm, __shfl_xor_sync(0xffffffffu, lm, 2, 8));
                lm = fmaxf(lm, __shfl_xor_sync(0xffffffffu, lm, 4, 8));
                stale_m = lm;
            }
            p0 = pn0; p1 = pn1;

            // gold score: uniform L1-hot gather + smem transition lookup
            gold += fbase[(tbase + u) * KTAG + tg] + sLogT[tg * 16 + prevtag];
            prevtag = tg;
        }

        #pragma unroll
        for (int u = 0; u < TILE; u++) { fA[u] = fB[u]; gA[u] = gB[u]; }
    }

    // forward = esum*ln2 + log( sum_j expT[STOP][j] * p_j )
    float v = Mstop0 * p0 + Mstop1 * p1;
    v += __shfl_xor_sync(0xffffffffu, v, 1, 8);
    v += __shfl_xor_sync(0xffffffffu, v, 2, 8);
    v += __shfl_xor_sync(0xffffffffu, v, 4, 8);

    double fwd = (double)esum * 0.6931471805599453 + (double)__logf(v);
    float goldT = gold + sLogT[STOP_TAG * 16 + prevtag];

    if (r == 0) out[b] = (float)(fwd - (double)goldT);
}

extern "C" void kernel_launch(void* const* d_in, const int* in_sizes, int n_in,
                              void* d_out, int out_size) {
    const float* feats = (const float*)d_in[0];
    const int*   tags  = (const int*)d_in[1];
    const float* trans = (const float*)d_in[2];
    float* out = (float*)d_out;

    int B = in_sizes[1] / T_LEN;           // 1024
    int blocks = B / 4;                    // 256 blocks x 1 warp, 4 elem/warp
    crf_nll_kernel<<<blocks, 32>>>(feats, tags, trans, out);
}

// round 11
// speedup vs baseline: 2.4731x; 2.4731x over previous
#include <cuda_runtime.h>

// CRF NLL: B=1024, T=4096, K=16 — bidirectional scan.
// fwd_score = log( u^T (D_T M)...(D_1 M) alpha0 ), u_j = exp(trans[STOP,j]).
// Forward half computes alpha_2048; backward half computes w_2049 where
// w_t = ef_t .* y_{t+1}, y_t = M^T w_t; then fwd_arg = w^T M alpha.
// Both halves use the proven R2 step (syncwarp smem exchange, exact pow2
// renorm with integer esum). A tiny combine kernel does the bilinear form.

#define T_LEN 4096
#define KTAG 16
#define TILE 16
#define START_TAG 14
#define STOP_TAG 15
#define NELEM 1024

__device__ float gBuf[NELEM][16];    // forward final alpha (scaled)
__device__ float wBuf[NELEM][16];    // backward final w (scaled)
__device__ int   eBufF[NELEM], eBufB[NELEM];
__device__ float goldBufF[NELEM], goldBufB[NELEM];

__global__ __launch_bounds__(128, 1)
void crf_scan_kernel(const float* __restrict__ feats,
                     const int* __restrict__ tags,
                     const float* __restrict__ trans) {
    __shared__ float sExpT[256];
    __shared__ float sLogT[256];
    __shared__ float sP[8][16];

    int tid = threadIdx.x;
    for (int i = tid; i < 256; i += 128) {
        float tv = trans[i];
        sLogT[i] = tv;
        sExpT[i] = __expf(tv);     // exp(-10000) -> 0: correct masking
    }

    int lane = tid & 31;
    int grp  = lane >> 4;
    int j    = lane & 15;
    int warp = tid >> 5;
    int g    = warp * 2 + grp;
    bool isFwd = (blockIdx.x < 128);
    int b = (isFwd ? blockIdx.x : blockIdx.x - 128) * 8 + g;

    __syncthreads();

    const float* fbase = feats + (size_t)b * T_LEN * KTAG;
    const int*   tptr  = tags  + (size_t)b * T_LEN;
    float* P = &sP[g][0];

    if (isFwd) {
        // ---------------- forward half: t = 1..2048 (idx 0..2047) ----------
        float Mr[16];
        #pragma unroll
        for (int i = 0; i < 16; i++) Mr[i] = sExpT[j * 16 + i];

        P[j] = (j == START_TAG) ? 1.0f : 0.0f;
        __syncthreads();

        int   esum = 0;
        float gold = 0.0f;
        int   prevtag = START_TAG;
        float pnew = 0.0f;

        float fA[TILE], fB[TILE];
        int   gA[TILE], gB[TILE];

        #pragma unroll
        for (int u = 0; u < TILE; u++) fA[u] = fbase[u * KTAG + j];
        {
            const int4* tp4 = reinterpret_cast<const int4*>(tptr);
            #pragma unroll
            for (int q = 0; q < 4; q++) {
                int4 v = tp4[q];
                gA[4*q+0] = v.x; gA[4*q+1] = v.y; gA[4*q+2] = v.z; gA[4*q+3] = v.w;
            }
        }

        const int NT = 2048 / TILE;   // 128
        #pragma unroll 1
        for (int tile = 0; tile < NT; tile++) {
            if (tile + 1 < NT) {
                int base = (tile + 1) * TILE;
                #pragma unroll
                for (int u = 0; u < TILE; u++) fB[u] = fbase[(base + u) * KTAG + j];
                const int4* tp4 = reinterpret_cast<const int4*>(tptr + base);
                #pragma unroll
                for (int q = 0; q < 4; q++) {
                    int4 v = tp4[q];
                    gB[4*q+0] = v.x; gB[4*q+1] = v.y; gB[4*q+2] = v.z; gB[4*q+3] = v.w;
                }
            }
            int tbase = tile * TILE;

            #pragma unroll
            for (int u = 0; u < TILE; u++) {
                float f  = fA[u];
                int   tg = gA[u];
                float ef = __expf(f);

                __syncwarp();
                float4 q0 = *reinterpret_cast<const float4*>(P + 0);
                float4 q1 = *reinterpret_cast<const float4*>(P + 4);
                float4 q2 = *reinterpret_cast<const float4*>(P + 8);
                float4 q3 = *reinterpret_cast<const float4*>(P + 12);

                if ((u & 3) == 3) {
                    float m0 = fmaxf(fmaxf(q0.x, q0.y), fmaxf(q0.z, q0.w));
                    float m1 = fmaxf(fmaxf(q1.x, q1.y), fmaxf(q1.z, q1.w));
                    float m2 = fmaxf(fmaxf(q2.x, q2.y), fmaxf(q2.z, q2.w));
                    float m3 = fmaxf(fmaxf(q3.x, q3.y), fmaxf(q3.z, q3.w));
                    float m  = fmaxf(fmaxf(m0, m1), fmaxf(m2, m3));
                    int e = (__float_as_int(m) >> 23) & 255;
                    ef *= __int_as_float((254 - e) << 23);   // 2^(127-e), exact
                    esum += e - 127;
                }

                float a0 = fmaf(q3.x, Mr[12], fmaf(q2.x, Mr[ 8], fmaf(q1.x, Mr[4], q0.x * Mr[0])));
                float a1 = fmaf(q3.y, Mr[13], fmaf(q2.y, Mr[ 9], fmaf(q1.y, Mr[5], q0.y * Mr[1])));
                float a2 = fmaf(q3.z, Mr[14], fmaf(q2.z, Mr[10], fmaf(q1.z, Mr[6], q0.z * Mr[2])));
                float a3 = fmaf(q3.w, Mr[15], fmaf(q2.w, Mr[11], fmaf(q1.w, Mr[7], q0.w * Mr[3])));
                pnew = ((a0 + a1) + (a2 + a3)) * ef;
                P[j] = pnew;

                gold += fbase[(tbase + u) * KTAG + tg] + sLogT[tg * 16 + prevtag];
                prevtag = tg;
            }

            #pragma unroll
            for (int u = 0; u < TILE; u++) { fA[u] = fB[u]; gA[u] = gB[u]; }
        }

        gBuf[b][j] = pnew;
        if (j == 0) { eBufF[b] = esum; goldBufF[b] = gold; }
    } else {
        // -------------- backward half: w <- ef .* (M^T w), idx 4094..2048 --
        float Mr[16];                 // row i of M^T = column j of M
        #pragma unroll
        for (int i = 0; i < 16; i++) Mr[i] = sExpT[i * 16 + j];

        // init: w_4096 = ef_4096 .* u, u_j = expT[STOP][j]
        int nt = tptr[4095];
        float gold = fbase[4095 * KTAG + nt] + sLogT[STOP_TAG * 16 + nt];
        P[j] = __expf(fbase[4095 * KTAG + j]) * sExpT[STOP_TAG * 16 + j];
        __syncthreads();

        int   esum = 0;
        float pnew = P[j];

        float fA[TILE], fB[TILE];
        int   gA[TILE], gB[TILE];

        // prime tile 0: d = 4094 - u
        #pragma unroll
        for (int u = 0; u < TILE; u++) fA[u] = fbase[(4094 - u) * KTAG + j];
        #pragma unroll
        for (int u = 0; u < TILE; u++) gA[u] = tptr[4094 - u];

        const int NTB = 128;          // tiles 0..126 full, tile 127 = 15 steps
        #pragma unroll 1
        for (int tile = 0; tile < NTB - 1; tile++) {
            {   // prefetch next tile (tile+1 <= 127; d=2047 slot harmlessly unused)
                int hi = 4094 - 16 * (tile + 1);
                #pragma unroll
                for (int u = 0; u < TILE; u++) fB[u] = fbase[(hi - u) * KTAG + j];
                #pragma unroll
                for (int u = 0; u < TILE; u++) gB[u] = tptr[hi - u];
            }
            int hi = 4094 - 16 * tile;

            #pragma unroll
            for (int u = 0; u < TILE; u++) {
                float f  = fA[u];
                int   tg = gA[u];
                float ef = __expf(f);

                __syncwarp();
                float4 q0 = *reinterpret_cast<const float4*>(P + 0);
                float4 q1 = *reinterpret_cast<const float4*>(P + 4);
                float4 q2 = *reinterpret_cast<const float4*>(P + 8);
                float4 q3 = *reinterpret_cast<const float4*>(P + 12);

                if ((u & 3) == 3) {
                    float m0 = fmaxf(fmaxf(q0.x, q0.y), fmaxf(q0.z, q0.w));
                    float m1 = fmaxf(fmaxf(q1.x, q1.y), fmaxf(q1.z, q1.w));
                    float m2 = fmaxf(fmaxf(q2.x, q2.y), fmaxf(q2.z, q2.w));
                    float m3 = fmaxf(fmaxf(q3.x, q3.y), fmaxf(q3.z, q3.w));
                    float m  = fmaxf(fmaxf(m0, m1), fmaxf(m2, m3));
                    int e = (__float_as_int(m) >> 23) & 255;
                    ef *= __int_as_float((254 - e) << 23);
                    esum += e - 127;
                }

                float a0 = fmaf(q3.x, Mr[12], fmaf(q2.x, Mr[ 8], fmaf(q1.x, Mr[4], q0.x * Mr[0])));
                float a1 = fmaf(q3.y, Mr[13], fmaf(q2.y, Mr[ 9], fmaf(q1.y, Mr[5], q0.y * Mr[1])));
                float a2 = fmaf(q3.z, Mr[14], fmaf(q2.z, Mr[10], fmaf(q1.z, Mr[6], q0.z * Mr[2])));
                float a3 = fmaf(q3.w, Mr[15], fmaf(q2.w, Mr[11], fmaf(q1.w, Mr[7], q0.w * Mr[3])));
                pnew = ((a0 + a1) + (a2 + a3)) * ef;
                P[j] = pnew;

                // descending gold: emit(d) + trans(tag_d -> tag_{d+1})
                gold += fbase[(hi - u) * KTAG + tg] + sLogT[nt * 16 + tg];
                nt = tg;
            }

            #pragma unroll
            for (int u = 0; u < TILE; u++) { fA[u] = fB[u]; gA[u] = gB[u]; }
        }

        // epilogue tile: 15 steps, d = 2062 - u (u = 0..14)
        #pragma unroll
        for (int u = 0; u < 15; u++) {
            float f  = fA[u];
            int   tg = gA[u];
            float ef = __expf(f);

            __syncwarp();
            float4 q0 = *reinterpret_cast<const float4*>(P + 0);
            float4 q1 = *reinterpret_cast<const float4*>(P + 4);
            float4 q2 = *reinterpret_cast<const float4*>(P + 8);
            float4 q3 = *reinterpret_cast<const float4*>(P + 12);

            if ((u & 3) == 3) {
                float m0 = fmaxf(fmaxf(q0.x, q0.y), fmaxf(q0.z, q0.w));
                float m1 = fmaxf(fmaxf(q1.x, q1.y), fmaxf(q1.z, q1.w));
                float m2 = fmaxf(fmaxf(q2.x, q2.y), fmaxf(q2.z, q2.w));
                float m3 = fmaxf(fmaxf(q3.x, q3.y), fmaxf(q3.z, q3.w));
                float m  = fmaxf(fmaxf(m0, m1), fmaxf(m2, m3));
                int e = (__float_as_int(m) >> 23) & 255;
                ef *= __int_as_float((254 - e) << 23);
                esum += e - 127;
            }

            float a0 = fmaf(q3.x, Mr[12], fmaf(q2.x, Mr[ 8], fmaf(q1.x, Mr[4], q0.x * Mr[0])));
            float a1 = fmaf(q3.y, Mr[13], fmaf(q2.y, Mr[ 9], fmaf(q1.y, Mr[5], q0.y * Mr[1])));
            float a2 = fmaf(q3.z, Mr[14], fmaf(q2.z, Mr[10], fmaf(q1.z, Mr[6], q0.z * Mr[2])));
            float a3 = fmaf(q3.w, Mr[15], fmaf(q2.w, Mr[11], fmaf(q1.w, Mr[7], q0.w * Mr[3])));
            pnew = ((a0 + a1) + (a2 + a3)) * ef;
            P[j] = pnew;

            gold += fbase[(2062 - u) * KTAG + tg] + sLogT[nt * 16 + tg];
            nt = tg;
        }

        // boundary transition: tag_2047 -> tag_2048 (nt == tags[2048] now)
        gold += sLogT[nt * 16 + tptr[2047]];

        wBuf[b][j] = pnew;
        if (j == 0) { eBufB[b] = esum; goldBufB[b] = gold; }
    }
}

__global__ void crf_combine_kernel(const float* __restrict__ trans,
                                   float* __restrict__ out) {
    __shared__ float sE[256];
    int t = threadIdx.x;          // 256 threads
    sE[t] = __expf(trans[t]);
    __syncthreads();

    int b = blockIdx.x * 256 + t;

    float gv[16], wv[16];
    #pragma unroll
    for (int i = 0; i < 16; i++) gv[i] = gBuf[b][i];
    #pragma unroll
    for (int i = 0; i < 16; i++) wv[i] = wBuf[b][i];

    // fwd_arg = w^T M g
    double dot = 0.0;
    #pragma unroll
    for (int jj = 0; jj < 16; jj++) {
        float mg = 0.0f;
        #pragma unroll
        for (int i = 0; i < 16; i++) mg = fmaf(sE[jj * 16 + i], gv[i], mg);
        dot += (double)wv[jj] * (double)mg;
    }

    double fwd = (double)(eBufF[b] + eBufB[b]) * 0.6931471805599453 + log(dot);
    out[b] = (float)(fwd - (double)goldBufF[b] - (double)goldBufB[b]);
}

extern "C" void kernel_launch(void* const* d_in, const int* in_sizes, int n_in,
                              void* d_out, int out_size) {
    const float* feats = (const float*)d_in[0];
    const int*   tags  = (const int*)d_in[1];
    const float* trans = (const float*)d_in[2];
    float* out = (float*)d_out;

    crf_scan_kernel<<<256, 128>>>(feats, tags, trans);
    crf_combine_kernel<<<4, 256>>>(trans, out);
}

// round 12
// speedup vs baseline: 2.6080x; 1.0546x over previous
#include <cuda_runtime.h>

// CRF NLL: B=1024, T=4096, K=16 — bidirectional scan + packed f32x2 matvec.
// Forward half computes alpha_2048 (prob domain, exact pow2 renorm);
// backward half computes w = ef .* (M^T w) down to index 2048;
// combine kernel evaluates fwd = log(w^T M alpha) + (esumF+esumB) ln2.
// Gold path score is computed by a dedicated per-block warp (warp 4) fully
// in parallel with the scan warps.

#define T_LEN 4096
#define KTAG 16
#define TILE 16
#define START_TAG 14
#define STOP_TAG 15
#define NELEM 1024

typedef unsigned long long ull;

__device__ float gBuf[NELEM][16];    // forward final alpha (scaled)
__device__ float wBuf[NELEM][16];    // backward final w (scaled)
__device__ int   eBufF[NELEM], eBufB[NELEM];
__device__ float goldBuf[NELEM];

__device__ __forceinline__ ull pk2(float lo, float hi) {
    ull d; asm("mov.b64 %0,{%1,%2};" : "=l"(d) : "f"(lo), "f"(hi)); return d;
}
__device__ __forceinline__ void upk2(ull v, float& lo, float& hi) {
    asm("mov.b64 {%0,%1},%2;" : "=f"(lo), "=f"(hi) : "l"(v));
}
__device__ __forceinline__ ull fma2(ull a, ull b, ull c) {
    ull d; asm("fma.rn.f32x2 %0,%1,%2,%3;" : "=l"(d) : "l"(a), "l"(b), "l"(c)); return d;
}
__device__ __forceinline__ ull mul2(ull a, ull b) {
    ull d; asm("mul.rn.f32x2 %0,%1,%2;" : "=l"(d) : "l"(a), "l"(b)); return d;
}
__device__ __forceinline__ ull add2(ull a, ull b) {
    ull d; asm("add.rn.f32x2 %0,%1,%2;" : "=l"(d) : "l"(a), "l"(b)); return d;
}

struct ULL2m { ull a, b; };
union Q16 { float4 f; ULL2m u; };

__global__ __launch_bounds__(160, 1)
void crf_scan_kernel(const float* __restrict__ feats,
                     const int* __restrict__ tags,
                     const float* __restrict__ trans) {
    __shared__ float sExpT[256];
    __shared__ float sLogT[256];
    __shared__ float sP[8][16];

    int tid = threadIdx.x;
    for (int i = tid; i < 256; i += 160) {
        float tv = trans[i];
        sLogT[i] = tv;
        sExpT[i] = __expf(tv);     // exp(-10000) -> 0: correct masking
    }
    __syncthreads();

    bool isFwd = (blockIdx.x < 128);
    int bblk = (isFwd ? blockIdx.x : blockIdx.x - 128) * 8;

    if (tid >= 128) {
        // ---------------- gold warp (fwd blocks only) ----------------------
        if (!isFwd) return;
        int lane = tid & 31;
        int g    = lane >> 2;          // element 0..7
        int sub  = lane & 3;           // quarter of the sequence
        int b    = bblk + g;
        const float* fbase = feats + (size_t)b * T_LEN * KTAG;
        const int*   tptr  = tags  + (size_t)b * T_LEN;

        int t0 = sub * 1024;
        int prev = (sub == 0) ? START_TAG : tptr[t0 - 1];
        float gg = 0.0f;
        for (int t = t0; t < t0 + 1024; t += 4) {
            int4 tg = *reinterpret_cast<const int4*>(tptr + t);
            float f0 = fbase[(t + 0) * KTAG + tg.x];
            float f1 = fbase[(t + 1) * KTAG + tg.y];
            float f2 = fbase[(t + 2) * KTAG + tg.z];
            float f3 = fbase[(t + 3) * KTAG + tg.w];
            gg += f0 + sLogT[tg.x * 16 + prev];
            gg += f1 + sLogT[tg.y * 16 + tg.x];
            gg += f2 + sLogT[tg.z * 16 + tg.y];
            gg += f3 + sLogT[tg.w * 16 + tg.z];
            prev = tg.w;
        }
        if (sub == 3) gg += sLogT[STOP_TAG * 16 + prev];   // terminal
        gg += __shfl_xor_sync(0xffffffffu, gg, 1, 4);
        gg += __shfl_xor_sync(0xffffffffu, gg, 2, 4);
        if (sub == 0) goldBuf[b] = gg;
        return;
    }

    // ------------------------- scan warps ---------------------------------
    int lane = tid & 31;
    int grp  = lane >> 4;
    int j    = lane & 15;
    int warp = tid >> 5;
    int g    = warp * 2 + grp;
    int b    = bblk + g;

    const float* fbase = feats + (size_t)b * T_LEN * KTAG;
    float* P = &sP[g][0];

    // packed row pairs: fwd uses rows of M, bwd uses rows of M^T
    ull Mp[8];
    if (isFwd) {
        #pragma unroll
        for (int k = 0; k < 8; k++)
            Mp[k] = pk2(sExpT[j * 16 + 2 * k], sExpT[j * 16 + 2 * k + 1]);
    } else {
        #pragma unroll
        for (int k = 0; k < 8; k++)
            Mp[k] = pk2(sExpT[(2 * k) * 16 + j], sExpT[(2 * k + 1) * 16 + j]);
    }

    if (isFwd) {
        P[j] = (j == START_TAG) ? 1.0f : 0.0f;
    } else {
        // w_4096 = ef_4096 .* u,  u_j = expT[STOP][j]
        P[j] = __expf(fbase[4095 * KTAG + j]) * sExpT[STOP_TAG * 16 + j];
    }
    __syncwarp();

    int   esum = 0;
    float pnew = isFwd ? 0.0f : P[j];

    float fA[TILE], fB[TILE];

    if (isFwd) {
        #pragma unroll
        for (int u = 0; u < TILE; u++) fA[u] = fbase[u * KTAG + j];

        const int NT = 2048 / TILE;   // 128
        #pragma unroll 1
        for (int tile = 0; tile < NT; tile++) {
            if (tile + 1 < NT) {
                int base = (tile + 1) * TILE;
                #pragma unroll
                for (int u = 0; u < TILE; u++) fB[u] = fbase[(base + u) * KTAG + j];
            }
            #pragma unroll
            for (int u = 0; u < TILE; u++) {
                float ef = __expf(fA[u]);
                __syncwarp();
                Q16 x0, x1, x2, x3;
                x0.f = *reinterpret_cast<const float4*>(P + 0);
                x1.f = *reinterpret_cast<const float4*>(P + 4);
                x2.f = *reinterpret_cast<const float4*>(P + 8);
                x3.f = *reinterpret_cast<const float4*>(P + 12);

                if ((u & 3) == 3) {
                    float m0 = fmaxf(fmaxf(x0.f.x, x0.f.y), fmaxf(x0.f.z, x0.f.w));
                    float m1 = fmaxf(fmaxf(x1.f.x, x1.f.y), fmaxf(x1.f.z, x1.f.w));
                    float m2 = fmaxf(fmaxf(x2.f.x, x2.f.y), fmaxf(x2.f.z, x2.f.w));
                    float m3 = fmaxf(fmaxf(x3.f.x, x3.f.y), fmaxf(x3.f.z, x3.f.w));
                    float m  = fmaxf(fmaxf(m0, m1), fmaxf(m2, m3));
                    int e = (__float_as_int(m) >> 23) & 255;
                    ef *= __int_as_float((254 - e) << 23);   // 2^(127-e), exact
                    esum += e - 127;
                }

                ull a0 = mul2(Mp[0], x0.u.a);
                ull a1 = mul2(Mp[1], x0.u.b);
                ull a2 = mul2(Mp[2], x1.u.a);
                ull a3 = mul2(Mp[3], x1.u.b);
                a0 = fma2(Mp[4], x2.u.a, a0);
                a1 = fma2(Mp[5], x2.u.b, a1);
                a2 = fma2(Mp[6], x3.u.a, a2);
                a3 = fma2(Mp[7], x3.u.b, a3);
                a0 = add2(a0, a1);
                a2 = add2(a2, a3);
                a0 = add2(a0, a2);
                float lo, hi; upk2(a0, lo, hi);
                pnew = (lo + hi) * ef;
                P[j] = pnew;
            }
            #pragma unroll
            for (int u = 0; u < TILE; u++) fA[u] = fB[u];
        }

        gBuf[b][j] = pnew;
        if (j == 0) eBufF[b] = esum;
    } else {
        // backward: idx 4094 down to 2048 (2047 steps: 127 full tiles + 15)
        #pragma unroll
        for (int u = 0; u < TILE; u++) fA[u] = fbase[(4094 - u) * KTAG + j];

        const int NTB = 128;
        #pragma unroll 1
        for (int tile = 0; tile < NTB - 1; tile++) {
            {
                int hi2 = 4094 - 16 * (tile + 1);
                #pragma unroll
                for (int u = 0; u < TILE; u++) fB[u] = fbase[(hi2 - u) * KTAG + j];
            }
            #pragma unroll
            for (int u = 0; u < TILE; u++) {
                float ef = __expf(fA[u]);
                __syncwarp();
                Q16 x0, x1, x2, x3;
                x0.f = *reinterpret_cast<const float4*>(P + 0);
                x1.f = *reinterpret_cast<const float4*>(P + 4);
                x2.f = *reinterpret_cast<const float4*>(P + 8);
                x3.f = *reinterpret_cast<const float4*>(P + 12);

                if ((u & 3) == 3) {
                    float m0 = fmaxf(fmaxf(x0.f.x, x0.f.y), fmaxf(x0.f.z, x0.f.w));
                    float m1 = fmaxf(fmaxf(x1.f.x, x1.f.y), fmaxf(x1.f.z, x1.f.w));
                    float m2 = fmaxf(fmaxf(x2.f.x, x2.f.y), fmaxf(x2.f.z, x2.f.w));
                    float m3 = fmaxf(fmaxf(x3.f.x, x3.f.y), fmaxf(x3.f.z, x3.f.w));
                    float m  = fmaxf(fmaxf(m0, m1), fmaxf(m2, m3));
                    int e = (__float_as_int(m) >> 23) & 255;
                    ef *= __int_as_float((254 - e) << 23);
                    esum += e - 127;
                }

                ull a0 = mul2(Mp[0], x0.u.a);
                ull a1 = mul2(Mp[1], x0.u.b);
                ull a2 = mul2(Mp[2], x1.u.a);
                ull a3 = mul2(Mp[3], x1.u.b);
                a0 = fma2(Mp[4], x2.u.a, a0);
                a1 = fma2(Mp[5], x2.u.b, a1);
                a2 = fma2(Mp[6], x3.u.a, a2);
                a3 = fma2(Mp[7], x3.u.b, a3);
                a0 = add2(a0, a1);
                a2 = add2(a2, a3);
                a0 = add2(a0, a2);
                float lo, hi; upk2(a0, lo, hi);
                pnew = (lo + hi) * ef;
                P[j] = pnew;
            }
            #pragma unroll
            for (int u = 0; u < TILE; u++) fA[u] = fB[u];
        }

        #pragma unroll
        for (int u = 0; u < 15; u++) {     // d = 2062 - u
            float ef = __expf(fA[u]);
            __syncwarp();
            Q16 x0, x1, x2, x3;
            x0.f = *reinterpret_cast<const float4*>(P + 0);
            x1.f = *reinterpret_cast<const float4*>(P + 4);
            x2.f = *reinterpret_cast<const float4*>(P + 8);
            x3.f = *reinterpret_cast<const float4*>(P + 12);

            if ((u & 3) == 3) {
                float m0 = fmaxf(fmaxf(x0.f.x, x0.f.y), fmaxf(x0.f.z, x0.f.w));
                float m1 = fmaxf(fmaxf(x1.f.x, x1.f.y), fmaxf(x1.f.z, x1.f.w));
                float m2 = fmaxf(fmaxf(x2.f.x, x2.f.y), fmaxf(x2.f.z, x2.f.w));
                float m3 = fmaxf(fmaxf(x3.f.x, x3.f.y), fmaxf(x3.f.z, x3.f.w));
                float m  = fmaxf(fmaxf(m0, m1), fmaxf(m2, m3));
                int e = (__float_as_int(m) >> 23) & 255;
                ef *= __int_as_float((254 - e) << 23);
                esum += e - 127;
            }

            ull a0 = mul2(Mp[0], x0.u.a);
            ull a1 = mul2(Mp[1], x0.u.b);
            ull a2 = mul2(Mp[2], x1.u.a);
            ull a3 = mul2(Mp[3], x1.u.b);
            a0 = fma2(Mp[4], x2.u.a, a0);
            a1 = fma2(Mp[5], x2.u.b, a1);
            a2 = fma2(Mp[6], x3.u.a, a2);
            a3 = fma2(Mp[7], x3.u.b, a3);
            a0 = add2(a0, a1);
            a2 = add2(a2, a3);
            a0 = add2(a0, a2);
            float lo, hi; upk2(a0, lo, hi);
            pnew = (lo + hi) * ef;
            P[j] = pnew;
        }

        wBuf[b][j] = pnew;
        if (j == 0) eBufB[b] = esum;
    }
}

__global__ void crf_combine_kernel(const float* __restrict__ trans,
                                   float* __restrict__ out) {
    __shared__ float sE[256];
    int t = threadIdx.x;
    sE[t] = __expf(trans[t]);
    __syncthreads();

    int b = blockIdx.x * 256 + t;

    float gv[16], wv[16];
    #pragma unroll
    for (int i = 0; i < 16; i++) gv[i] = gBuf[b][i];
    #pragma unroll
    for (int i = 0; i < 16; i++) wv[i] = wBuf[b][i];

    // fwd_arg = w^T M alpha
    double dot = 0.0;
    #pragma unroll
    for (int jj = 0; jj < 16; jj++) {
        float mg = 0.0f;
        #pragma unroll
        for (int i = 0; i < 16; i++) mg = fmaf(sE[jj * 16 + i], gv[i], mg);
        dot += (double)wv[jj] * (double)mg;
    }

    double fwd = (double)(eBufF[b] + eBufB[b]) * 0.6931471805599453 + log(dot);
    out[b] = (float)(fwd - (double)goldBuf[b]);
}

extern "C" void kernel_launch(void* const* d_in, const int* in_sizes, int n_in,
                              void* d_out, int out_size) {
    const float* feats = (const float*)d_in[0];
    const int*   tags  = (const int*)d_in[1];
    const float* trans = (const float*)d_in[2];
    float* out = (float*)d_out;

    crf_scan_kernel<<<256, 160>>>(feats, tags, trans);
    crf_combine_kernel<<<4, 256>>>(trans, out);
}